// round 3
// baseline (speedup 1.0000x reference)
#include <cuda_runtime.h>
#include <math.h>

// ---------------- problem constants ----------------
#define BATCH 8
#define CCH   2
#define HF    128
#define INC   512
#define NPTS  128          // N
#define NCAND 384          // 3*N over-generated candidates
#define NIMP  96           // importance points
#define NRAND 16
#define MROWS (BATCH*NPTS) // 1024
#define K1    514          // in_c + C
#define H1    512
#define H2    256

// ---------------- static scratch (no allocs allowed) ----------------
__device__ float g_points[BATCH*NPTS*2];
__device__ float g_feat [MROWS*K1];
__device__ float g_coarse[BATCH*CCH*NPTS];
__device__ float g_buf1 [MROWS*H1];
__device__ float g_buf2 [MROWS*H2];

// order-preserving float -> uint encoding
__device__ __forceinline__ unsigned int fenc(float v) {
    unsigned int u = __float_as_uint(v);
    return (u & 0x80000000u) ? ~u : (u | 0x80000000u);
}

// =====================================================================
// Kernel 1: sampling-point selection.
//  - per candidate: bilinear sample of per-pixel (max,min) of out channels
//    (sort-then-sample), unc = sampled(min) - sampled(max)
//  - exact lax.top_k(96) ordering via O(384^2) strict-rank counting
//  - coverage points are provably (0,0) (trunc of <1 values) -> write zeros
// =====================================================================
__global__ void k_points(const float* __restrict__ out,
                         const float* __restrict__ over_gen,
                         const float* __restrict__ rand_point,
                         float* __restrict__ pts_out, int write_out)
{
    int b = blockIdx.x;
    int t = threadIdx.x;
    __shared__ unsigned long long keys[NCAND];

    if (t < NCAND) {
        float px = over_gen[(b*NCAND + t)*2 + 0];
        float py = over_gen[(b*NCAND + t)*2 + 1];
        float gx = px * HF - 0.5f;
        float gy = py * HF - 0.5f;
        float x0f = floorf(gx), y0f = floorf(gy);
        float wx = gx - x0f, wy = gy - y0f;
        int x0 = (int)x0f, y0 = (int)y0f;
        const float* o0 = out + (size_t)b*CCH*HF*HF;
        const float* o1 = o0 + HF*HF;
        float unc = 0.f;
        #pragma unroll
        for (int dy = 0; dy < 2; dy++) {
            #pragma unroll
            for (int dx = 0; dx < 2; dx++) {
                int xi = x0 + dx, yi = y0 + dy;
                bool valid = (xi >= 0) && (xi < HF) && (yi >= 0) && (yi < HF);
                int xc = min(max(xi, 0), HF-1);
                int yc = min(max(yi, 0), HF-1);
                float a = o0[yc*HF + xc];
                float c = o1[yc*HF + xc];
                float w = (dx ? wx : 1.f - wx) * (dy ? wy : 1.f - wy);
                if (valid) unc += w * (fminf(a, c) - fmaxf(a, c));
            }
        }
        keys[t] = (((unsigned long long)fenc(unc)) << 32)
                | (unsigned long long)(1023 - t);   // smaller idx -> bigger key on ties
    }
    __syncthreads();

    if (t < NCAND) {
        unsigned long long mine = keys[t];
        int rank = 0;
        #pragma unroll 8
        for (int j = 0; j < NCAND; j++) rank += (keys[j] > mine);
        if (rank < NIMP) {
            float px = over_gen[(b*NCAND + t)*2 + 0];
            float py = over_gen[(b*NCAND + t)*2 + 1];
            g_points[(b*NPTS + rank)*2 + 0] = px;
            g_points[(b*NPTS + rank)*2 + 1] = py;
            if (write_out) {
                pts_out[(b*NPTS + rank)*2 + 0] = px;
                pts_out[(b*NPTS + rank)*2 + 1] = py;
            }
        }
    }
    if (t < NRAND) {
        int i = NIMP + t;          // coverage: always (0,0)
        int j = NIMP + NRAND + t;  // random points
        float rx = rand_point[(b*NRAND + t)*2 + 0];
        float ry = rand_point[(b*NRAND + t)*2 + 1];
        g_points[(b*NPTS + i)*2 + 0] = 0.f;
        g_points[(b*NPTS + i)*2 + 1] = 0.f;
        g_points[(b*NPTS + j)*2 + 0] = rx;
        g_points[(b*NPTS + j)*2 + 1] = ry;
        if (write_out) {
            pts_out[(b*NPTS + i)*2 + 0] = 0.f;
            pts_out[(b*NPTS + i)*2 + 1] = 0.f;
            pts_out[(b*NPTS + j)*2 + 0] = rx;
            pts_out[(b*NPTS + j)*2 + 1] = ry;
        }
    }
}

// =====================================================================
// Kernel 2: fused coarse+fine bilinear gather -> feat rows [coarse(2) | fine(512)]
// one block per (b, n); threads stride channels
// =====================================================================
__global__ void k_gather(const float* __restrict__ res2,
                         const float* __restrict__ out)
{
    int n = blockIdx.x, b = blockIdx.y;
    int row = b*NPTS + n;
    float px = g_points[row*2 + 0];
    float py = g_points[row*2 + 1];
    float gx = px*HF - 0.5f, gy = py*HF - 0.5f;
    float x0f = floorf(gx), y0f = floorf(gy);
    float wx = gx - x0f, wy = gy - y0f;
    int x0 = (int)x0f, y0 = (int)y0f;
    int x1 = x0 + 1, y1 = y0 + 1;
    float vx0 = (x0 >= 0 && x0 < HF) ? 1.f : 0.f;
    float vx1 = (x1 >= 0 && x1 < HF) ? 1.f : 0.f;
    float vy0 = (y0 >= 0 && y0 < HF) ? 1.f : 0.f;
    float vy1 = (y1 >= 0 && y1 < HF) ? 1.f : 0.f;
    int xc0 = min(max(x0, 0), HF-1), xc1 = min(max(x1, 0), HF-1);
    int yc0 = min(max(y0, 0), HF-1), yc1 = min(max(y1, 0), HF-1);
    float w00 = (1.f-wx)*(1.f-wy)*vx0*vy0;
    float w10 = wx*(1.f-wy)*vx1*vy0;
    float w01 = (1.f-wx)*wy*vx0*vy1;
    float w11 = wx*wy*vx1*vy1;
    int i00 = yc0*HF + xc0, i10 = yc0*HF + xc1;
    int i01 = yc1*HF + xc0, i11 = yc1*HF + xc1;

    for (int c = threadIdx.x; c < INC; c += blockDim.x) {
        const float* p = res2 + ((size_t)(b*INC + c))*HF*HF;
        float v = w00*__ldg(p + i00) + w10*__ldg(p + i10)
                + w01*__ldg(p + i01) + w11*__ldg(p + i11);
        g_feat[(size_t)row*K1 + CCH + c] = v;
    }
    if (threadIdx.x < CCH) {
        int c = threadIdx.x;
        const float* p = out + ((size_t)(b*CCH + c))*HF*HF;
        float v = w00*p[i00] + w10*p[i10] + w01*p[i01] + w11*p[i11];
        g_feat[(size_t)row*K1 + c] = v;
        g_coarse[(b*CCH + c)*NPTS + n] = v;
    }
}

// =====================================================================
// Tiled fp32 GEMM + bias: C[M,N] = A[M,K] @ B[K,N] + bias  (row-major)
// =====================================================================
template<int BM, int BN, int BK, int TM, int TN>
__global__ __launch_bounds__(256)
void sgemm_bias(const float* __restrict__ A, const float* __restrict__ B,
                const float* __restrict__ bias, float* __restrict__ C,
                int M, int N, int K)
{
    __shared__ float As[BK][BM + 1];
    __shared__ float Bs[BK][BN];
    const int TX = BN / TN;
    int tid = threadIdx.x;
    int tx = tid % TX, ty = tid / TX;
    int bm = blockIdx.y * BM, bn = blockIdx.x * BN;
    float acc[TM][TN];
    #pragma unroll
    for (int i = 0; i < TM; i++)
        #pragma unroll
        for (int j = 0; j < TN; j++) acc[i][j] = 0.f;

    for (int k0 = 0; k0 < K; k0 += BK) {
        #pragma unroll
        for (int i = tid; i < BM*BK; i += 256) {
            int m = i / BK, kk = i % BK;
            int gk = k0 + kk;
            As[kk][m] = (gk < K) ? A[(size_t)(bm + m)*K + gk] : 0.f;
        }
        #pragma unroll
        for (int i = tid; i < BK*BN; i += 256) {
            int kk = i / BN, nn = i % BN;
            int gk = k0 + kk;
            Bs[kk][nn] = (gk < K) ? B[(size_t)gk*N + bn + nn] : 0.f;
        }
        __syncthreads();
        #pragma unroll
        for (int kk = 0; kk < BK; kk++) {
            float ra[TM], rb[TN];
            #pragma unroll
            for (int i = 0; i < TM; i++) ra[i] = As[kk][ty*TM + i];
            #pragma unroll
            for (int j = 0; j < TN; j++) rb[j] = Bs[kk][tx*TN + j];
            #pragma unroll
            for (int i = 0; i < TM; i++)
                #pragma unroll
                for (int j = 0; j < TN; j++)
                    acc[i][j] += ra[i] * rb[j];
        }
        __syncthreads();
    }
    #pragma unroll
    for (int i = 0; i < TM; i++) {
        int m = bm + ty*TM + i;
        #pragma unroll
        for (int j = 0; j < TN; j++) {
            int nn = bn + tx*TN + j;
            C[(size_t)m*N + nn] = acc[i][j] + bias[nn];
        }
    }
}

// =====================================================================
// LayerNorm (two-pass, matches jnp mean/var) + exact GELU, in-place
// =====================================================================
__device__ __forceinline__ float block_sum(float v, float* red)
{
    int lane = threadIdx.x & 31, w = threadIdx.x >> 5;
    #pragma unroll
    for (int o = 16; o > 0; o >>= 1) v += __shfl_down_sync(0xFFFFFFFFu, v, o);
    if (lane == 0) red[w] = v;
    __syncthreads();
    int nw = blockDim.x >> 5;
    float s = (threadIdx.x < nw) ? red[threadIdx.x] : 0.f;
    if (w == 0) {
        #pragma unroll
        for (int o = 16; o > 0; o >>= 1) s += __shfl_down_sync(0xFFFFFFFFu, s, o);
        if (lane == 0) red[0] = s;
    }
    __syncthreads();
    float r = red[0];
    __syncthreads();
    return r;
}

template<int D>
__global__ void ln_gelu(float* __restrict__ X,
                        const float* __restrict__ gw, const float* __restrict__ bw)
{
    __shared__ float sx[D];
    __shared__ float red[32];
    float* x = X + (size_t)blockIdx.x * D;
    int t = threadIdx.x;
    float s = 0.f;
    for (int d = t; d < D; d += blockDim.x) { float v = x[d]; sx[d] = v; s += v; }
    float mean = block_sum(s, red) * (1.f / D);
    float s2 = 0.f;
    for (int d = t; d < D; d += blockDim.x) { float dv = sx[d] - mean; s2 += dv*dv; }
    float var = block_sum(s2, red) * (1.f / D);
    float inv = rsqrtf(var + 1e-5f);
    for (int d = t; d < D; d += blockDim.x) {
        float y = (sx[d] - mean) * inv * gw[d] + bw[d];
        x[d] = 0.5f * y * (1.f + erff(y * 0.70710678118654752f));
    }
}

// =====================================================================
// Final: pred = h2 @ w3 + b3 ; rend = pred * mask + coarse
// one warp per row
// =====================================================================
__global__ void k_final(const float* __restrict__ w3, const float* __restrict__ b3,
                        const float* __restrict__ mask, float* __restrict__ rend)
{
    int warp = threadIdx.x >> 5, lane = threadIdx.x & 31;
    int row = blockIdx.x * 8 + warp;
    const float* h = g_buf2 + (size_t)row * H2;
    float p0 = 0.f, p1 = 0.f;
    #pragma unroll
    for (int k = lane; k < H2; k += 32) {
        float hv = h[k];
        p0 += hv * w3[k*2 + 0];
        p1 += hv * w3[k*2 + 1];
    }
    #pragma unroll
    for (int o = 16; o > 0; o >>= 1) {
        p0 += __shfl_down_sync(0xFFFFFFFFu, p0, o);
        p1 += __shfl_down_sync(0xFFFFFFFFu, p1, o);
    }
    if (lane == 0) {
        int b = row / NPTS, n = row % NPTS;
        int i0 = (b*CCH + 0)*NPTS + n;
        int i1 = (b*CCH + 1)*NPTS + n;
        rend[i0] = (p0 + b3[0]) * mask[i0] + g_coarse[i0];
        rend[i1] = (p1 + b3[1]) * mask[i1] + g_coarse[i1];
    }
}

// =====================================================================
extern "C" void kernel_launch(void* const* d_in, const int* in_sizes, int n_in,
                              void* d_out, int out_size)
{
    // metadata order: x, res2, out, over_gen, rand_point, dropout_mask,
    //                 w1,b1,g1,be1, w2,b2,g2,be2, w3,b3
    const float* res2       = (const float*)d_in[1];
    const float* out        = (const float*)d_in[2];
    const float* over_gen   = (const float*)d_in[3];
    const float* rand_point = (const float*)d_in[4];
    const float* mask       = (const float*)d_in[5];
    const float* w1  = (const float*)d_in[6];
    const float* b1  = (const float*)d_in[7];
    const float* gm1 = (const float*)d_in[8];
    const float* be1 = (const float*)d_in[9];
    const float* w2  = (const float*)d_in[10];
    const float* b2  = (const float*)d_in[11];
    const float* gm2 = (const float*)d_in[12];
    const float* be2 = (const float*)d_in[13];
    const float* w3  = (const float*)d_in[14];
    const float* b3  = (const float*)d_in[15];

    float* rend = (float*)d_out;
    int has_pts = (out_size >= BATCH*CCH*NPTS + BATCH*NPTS*2) ? 1 : 0;
    float* pts  = rend + BATCH*CCH*NPTS;

    // resolve device-symbol addresses for GEMM args (host API, capture-safe)
    float *p_feat, *p_buf1, *p_buf2;
    cudaGetSymbolAddress((void**)&p_feat, g_feat);
    cudaGetSymbolAddress((void**)&p_buf1, g_buf1);
    cudaGetSymbolAddress((void**)&p_buf2, g_buf2);

    k_points<<<BATCH, NCAND>>>(out, over_gen, rand_point, pts, has_pts);

    dim3 gg(NPTS, BATCH);
    k_gather<<<gg, 256>>>(res2, out);

    // GEMM1: [1024,514] @ [514,512]
    {
        dim3 grid(H1/64, MROWS/64);
        sgemm_bias<64,64,16,4,4><<<grid, 256>>>(p_feat, w1, b1, p_buf1, MROWS, H1, K1);
    }
    ln_gelu<H1><<<MROWS, 256>>>(p_buf1, gm1, be1);

    // GEMM2: [1024,512] @ [512,256]
    {
        dim3 grid(H2/64, MROWS/32);
        sgemm_bias<32,64,16,2,4><<<grid, 256>>>(p_buf1, w2, b2, p_buf2, MROWS, H2, H1);
    }
    ln_gelu<H2><<<MROWS, 256>>>(p_buf2, gm2, be2);

    k_final<<<MROWS/8, 256>>>(w3, b3, mask, rend);
}